// round 7
// baseline (speedup 1.0000x reference)
#include <cuda_runtime.h>

#define B 128
#define K 17
#define HW 9216          // 96*96
#define NVEC (HW/4)      // 2304
#define TOPK 8
#define THREADS1 256
#define NTILES (B * K)   // 2176
#define GRIDX 888        // 148 SMs * 6 resident blocks -> single wave

__device__ float g_per_joint[B * K];
__device__ unsigned int g_counter = 0;

__global__ void __launch_bounds__(THREADS1, 6)   // force <=42 regs -> 6 blocks/SM
mse_ohkm_persistent_kernel(const float* __restrict__ pred,
                           const float* __restrict__ gt,
                           const float* __restrict__ tw,
                           float* __restrict__ out) {
    const int tid  = threadIdx.x;
    const int lane = tid & 31;
    const int wid  = tid >> 5;
    __shared__ float warp_sums[THREADS1 / 32];
    __shared__ unsigned int is_last;

    // ---- persistent loop: each block handles tiles bk, bk+888, ... ----
    for (int bk = blockIdx.x; bk < NTILES; bk += GRIDX) {
        const float4* __restrict__ p = reinterpret_cast<const float4*>(pred + (size_t)bk * HW);
        const float4* __restrict__ g = reinterpret_cast<const float4*>(gt   + (size_t)bk * HW);

        float acc = 0.0f;
        #pragma unroll
        for (int j = 0; j < NVEC / THREADS1; j++) {   // 9 iterations
            const int i = tid + j * THREADS1;
            float4 a = p[i];
            float4 b = g[i];
            float d0 = a.x - b.x;
            float d1 = a.y - b.y;
            float d2 = a.z - b.z;
            float d3 = a.w - b.w;
            acc += d0 * d0 + d1 * d1 + d2 * d2 + d3 * d3;
        }

        #pragma unroll
        for (int off = 16; off > 0; off >>= 1)
            acc += __shfl_down_sync(0xFFFFFFFFu, acc, off);

        if (lane == 0) warp_sums[wid] = acc;
        __syncthreads();

        if (wid == 0) {
            float v = (lane < THREADS1 / 32) ? warp_sums[lane] : 0.0f;
            #pragma unroll
            for (int off = 4; off > 0; off >>= 1)
                v += __shfl_down_sync(0xFFFFFFFFu, v, off);
            if (lane == 0) {
                const float w = tw[bk];
                g_per_joint[bk] = v * w * w * (1.0f / (float)HW);
            }
        }
        __syncthreads();   // warp_sums reused next iteration
    }

    // ---- one release-atomic per block ----
    if (tid == 0) {
        unsigned int old;
        asm volatile("atom.add.release.gpu.global.u32 %0, [%1], 1;"
                     : "=r"(old) : "l"(&g_counter) : "memory");
        is_last = (old == (unsigned int)(GRIDX - 1)) ? 1u : 0u;
    }
    __syncthreads();
    if (!is_last) return;

    // ---- last block: OHKM top-k over L2-hot per-joint values ----
    // Register-lean tail: K loop NOT unrolled so it doesn't inflate the
    // kernel-wide register allocation (runs once, in one block).
    asm volatile("fence.acq_rel.gpu;" ::: "memory");

    __shared__ float sh[B];
    if (tid < B) {
        float t[TOPK];
        #pragma unroll
        for (int j = 0; j < TOPK; j++) t[j] = -3.4e38f;

        #pragma unroll 1
        for (int i = 0; i < K; i++) {
            float x = __ldcg(&g_per_joint[tid * K + i]);
            #pragma unroll
            for (int j = 0; j < TOPK; j++) {
                float old = t[j];
                bool gtp = x > old;
                t[j] = gtp ? x : old;
                x    = gtp ? old : x;
            }
        }
        float s = 0.0f;
        #pragma unroll
        for (int j = 0; j < TOPK; j++) s += t[j];
        sh[tid] = s;
    }
    __syncthreads();

    #pragma unroll
    for (int stride = B / 2; stride > 0; stride >>= 1) {
        if (tid < stride) sh[tid] += sh[tid + stride];
        __syncthreads();
    }
    if (tid == 0) {
        out[0] = sh[0] * (1.0f / (float)(B * TOPK));
        g_counter = 0u;   // reset for next graph replay
    }
}

extern "C" void kernel_launch(void* const* d_in, const int* in_sizes, int n_in,
                              void* d_out, int out_size) {
    const float* pred = (const float*)d_in[0];   // output [B,K,H,W]
    const float* gt   = (const float*)d_in[1];   // target [B,K,H,W]
    const float* tw   = (const float*)d_in[2];   // target_weight [B,K,1]
    float* out = (float*)d_out;

    mse_ohkm_persistent_kernel<<<GRIDX, THREADS1>>>(pred, gt, tw, out);
}